// round 5
// baseline (speedup 1.0000x reference)
#include <cuda_runtime.h>
#include <math.h>

#define BATCH   1024
#define SEQ     200
#define HID     128
#define VOCAB   100000
#define PAD_ID      99998
#define INTEREST_ID 99999
#define NTHR    256
#define ROW4    (VOCAB / 4)      // 25000 float4 per output row

// scratch: per-(b,s) attention weight (0 for masked positions)
__device__ float g_weights[BATCH * SEQ];

// ---------------------------------------------------------------------------
// Kernel 1: pure-read stream. scores -> masked softmax -> weights scratch.
// ---------------------------------------------------------------------------
__global__ __launch_bounds__(NTHR) void score_kernel(
    const float* __restrict__ hs,   // (B, S, H) fp32
    const int*   __restrict__ ids,  // (B, S) int32
    const float* __restrict__ w,    // (H,)
    const float* __restrict__ bp)   // (1,)
{
    const int b    = blockIdx.x;
    const int tid  = threadIdx.x;
    const int lane = tid & 31;
    const int warp = tid >> 5;

    __shared__ float s_scores[SEQ];
    __shared__ float red[8];

    // lane l owns H-elements [4l, 4l+4)
    const float4* hb  = reinterpret_cast<const float4*>(hs + (size_t)b * SEQ * HID);
    const float4  key = hb[lane];                               // hidden[b,0,:]
    const float4  wp  = reinterpret_cast<const float4*>(w)[lane];
    const float   bias = bp[0];

    #pragma unroll 1
    for (int j = 0; j < 25; ++j) {
        const int s = warp + 8 * j;
        float4 hv = hb[s * (HID / 4) + lane];
        float p = tanhf(hv.x + key.x) * wp.x
                + tanhf(hv.y + key.y) * wp.y
                + tanhf(hv.z + key.z) * wp.z
                + tanhf(hv.w + key.w) * wp.w;
        #pragma unroll
        for (int o = 16; o; o >>= 1) p += __shfl_xor_sync(0xffffffffu, p, o);
        if (lane == 0) s_scores[s] = p + bias;
    }
    __syncthreads();

    // masked softmax over S (thread t owns position t)
    int   my_id    = 0;
    bool  my_valid = false;
    float my_sc    = -INFINITY;
    if (tid < SEQ) {
        my_id    = ids[(size_t)b * SEQ + tid];
        my_valid = (my_id != PAD_ID) && (my_id != INTEREST_ID);
        my_sc    = my_valid ? s_scores[tid] : -INFINITY;
    }

    float m = my_sc;
    #pragma unroll
    for (int o = 16; o; o >>= 1) m = fmaxf(m, __shfl_xor_sync(0xffffffffu, m, o));
    if (lane == 0) red[warp] = m;
    __syncthreads();
    if (warp == 0) {
        float mm = red[lane & 7];
        #pragma unroll
        for (int o = 4; o; o >>= 1) mm = fmaxf(mm, __shfl_xor_sync(0xffffffffu, mm, o));
        if (lane == 0) red[0] = mm;
    }
    __syncthreads();
    m = red[0];

    float e = (tid < SEQ && my_valid) ? expf(my_sc - m) : 0.f;
    float ssum = e;
    #pragma unroll
    for (int o = 16; o; o >>= 1) ssum += __shfl_xor_sync(0xffffffffu, ssum, o);
    __syncthreads();
    if (lane == 0) red[warp] = ssum;
    __syncthreads();
    if (warp == 0) {
        float tt = red[lane & 7];
        #pragma unroll
        for (int o = 4; o; o >>= 1) tt += __shfl_xor_sync(0xffffffffu, tt, o);
        if (lane == 0) red[0] = tt;
    }
    __syncthreads();
    const float inv_sum = 1.0f / red[0];

    if (tid < SEQ) {
        g_weights[(size_t)b * SEQ + tid] = my_valid ? e * inv_sum : 0.f;
    }
}

// ---------------------------------------------------------------------------
// Kernel 2: pure-write stream. zero output row, then scatter weights.
// ---------------------------------------------------------------------------
__global__ __launch_bounds__(NTHR) void zero_scatter_kernel(
    const int* __restrict__ ids,    // (B, S) int32
    float* __restrict__ out)        // (B, VOCAB) fp32
{
    const int b   = blockIdx.x;
    const int tid = threadIdx.x;

    float* row = out + (size_t)b * VOCAB;
    float4* row4 = reinterpret_cast<float4*>(row);
    const float4 z = make_float4(0.f, 0.f, 0.f, 0.f);

    #pragma unroll 8
    for (int i = tid; i < ROW4; i += NTHR) row4[i] = z;
    __syncthreads();

    if (tid < SEQ) {
        float wgt = g_weights[(size_t)b * SEQ + tid];
        if (wgt != 0.f) {
            int id = ids[(size_t)b * SEQ + tid];
            atomicAdd(row + id, wgt);
        }
    }
}

extern "C" void kernel_launch(void* const* d_in, const int* in_sizes, int n_in,
                              void* d_out, int out_size) {
    const float* hs  = (const float*)d_in[0];
    const int*   ids = (const int*)d_in[1];
    const float* w   = (const float*)d_in[2];
    const float* bp  = (const float*)d_in[3];
    float*       out = (float*)d_out;

    score_kernel<<<BATCH, NTHR>>>(hs, ids, w, bp);
    zero_scatter_kernel<<<BATCH, NTHR>>>(ids, out);
}

// round 6
// speedup vs baseline: 1.4258x; 1.4258x over previous
#include <cuda_runtime.h>
#include <math.h>

#define BATCH   1024
#define SEQ     200
#define HID     128
#define VOCAB   100000
#define PAD_ID      99998
#define INTEREST_ID 99999
#define NTHR    256

// ---------------------------------------------------------------------------
// Fused: scores -> masked softmax -> scatter-add into (pre-zeroed) output.
// One CTA per batch row. ~106 MB of reads, 205K spread atomics. No big writes.
// ---------------------------------------------------------------------------
__global__ __launch_bounds__(NTHR) void score_scatter_kernel(
    const float* __restrict__ hs,   // (B, S, H) fp32
    const int*   __restrict__ ids,  // (B, S) int32
    const float* __restrict__ w,    // (H,)
    const float* __restrict__ bp,   // (1,)
    float* __restrict__ out)        // (B, VOCAB) fp32, already zeroed
{
    const int b    = blockIdx.x;
    const int tid  = threadIdx.x;
    const int lane = tid & 31;
    const int warp = tid >> 5;

    __shared__ float s_scores[SEQ];
    __shared__ float red[8];

    // lane l owns H-elements [4l, 4l+4)
    const float4* hb  = reinterpret_cast<const float4*>(hs + (size_t)b * SEQ * HID);
    const float4  key = hb[lane];                               // hidden[b,0,:]
    const float4  wp  = reinterpret_cast<const float4*>(w)[lane];
    const float   bias = bp[0];

    #pragma unroll 1
    for (int j = 0; j < 25; ++j) {
        const int s = warp + 8 * j;
        float4 hv = hb[s * (HID / 4) + lane];
        float p = tanhf(hv.x + key.x) * wp.x
                + tanhf(hv.y + key.y) * wp.y
                + tanhf(hv.z + key.z) * wp.z
                + tanhf(hv.w + key.w) * wp.w;
        #pragma unroll
        for (int o = 16; o; o >>= 1) p += __shfl_xor_sync(0xffffffffu, p, o);
        if (lane == 0) s_scores[s] = p + bias;
    }
    __syncthreads();

    // masked softmax over S (thread t owns position t)
    int   my_id    = 0;
    bool  my_valid = false;
    float my_sc    = -INFINITY;
    if (tid < SEQ) {
        my_id    = ids[(size_t)b * SEQ + tid];
        my_valid = (my_id != PAD_ID) && (my_id != INTEREST_ID);
        my_sc    = my_valid ? s_scores[tid] : -INFINITY;
    }

    // block-reduce max
    float m = my_sc;
    #pragma unroll
    for (int o = 16; o; o >>= 1) m = fmaxf(m, __shfl_xor_sync(0xffffffffu, m, o));
    if (lane == 0) red[warp] = m;
    __syncthreads();
    if (warp == 0) {
        float mm = red[lane & 7];
        #pragma unroll
        for (int o = 4; o; o >>= 1) mm = fmaxf(mm, __shfl_xor_sync(0xffffffffu, mm, o));
        if (lane == 0) red[0] = mm;
    }
    __syncthreads();
    m = red[0];

    // exp and block-reduce sum
    float e = (tid < SEQ && my_valid) ? expf(my_sc - m) : 0.f;
    float ssum = e;
    #pragma unroll
    for (int o = 16; o; o >>= 1) ssum += __shfl_xor_sync(0xffffffffu, ssum, o);
    __syncthreads();
    if (lane == 0) red[warp] = ssum;
    __syncthreads();
    if (warp == 0) {
        float tt = red[lane & 7];
        #pragma unroll
        for (int o = 4; o; o >>= 1) tt += __shfl_xor_sync(0xffffffffu, tt, o);
        if (lane == 0) red[0] = tt;
    }
    __syncthreads();
    const float inv_sum = 1.0f / red[0];

    // scatter into this block's private (pre-zeroed) row
    if (tid < SEQ && my_valid) {
        atomicAdd(out + (size_t)b * VOCAB + my_id, e * inv_sum);
    }
}

extern "C" void kernel_launch(void* const* d_in, const int* in_sizes, int n_in,
                              void* d_out, int out_size) {
    const float* hs  = (const float*)d_in[0];
    const int*   ids = (const int*)d_in[1];
    const float* w   = (const float*)d_in[2];
    const float* bp  = (const float*)d_in[3];
    float*       out = (float*)d_out;

    // Driver-tuned zero-fill of the 410 MB output (graph memset node).
    cudaMemsetAsync(out, 0, (size_t)out_size * sizeof(float));

    // Reads + scatter; ordered after the memset by stream order.
    score_scatter_kernel<<<BATCH, NTHR>>>(hs, ids, w, bp, out);
}

// round 8
// speedup vs baseline: 1.4587x; 1.0231x over previous
#include <cuda_runtime.h>
#include <math.h>

#define BATCH   1024
#define SEQ     200
#define HID     128
#define VOCAB   100000
#define PAD_ID      99998
#define INTEREST_ID 99999
#define NTHR    256

__device__ __forceinline__ float fast_tanh(float x) {
    float y;
    asm("tanh.approx.f32 %0, %1;" : "=f"(y) : "f"(x));
    return y;
}

// ---------------------------------------------------------------------------
// Fused: scores -> masked softmax -> scatter-add into (pre-zeroed) output.
// One CTA per batch row. ~106 MB of reads, 205K spread atomics.
// ---------------------------------------------------------------------------
__global__ __launch_bounds__(NTHR) void score_scatter_kernel(
    const float* __restrict__ hs,   // (B, S, H) fp32
    const int*   __restrict__ ids,  // (B, S) int32
    const float* __restrict__ w,    // (H,)
    const float* __restrict__ bp,   // (1,)
    float* __restrict__ out)        // (B, VOCAB) fp32, already zeroed
{
    const int b    = blockIdx.x;
    const int tid  = threadIdx.x;
    const int lane = tid & 31;
    const int warp = tid >> 5;

    __shared__ float s_scores[SEQ];
    __shared__ float red[8];

    // lane l owns H-elements [4l, 4l+4)
    const float4* hb  = reinterpret_cast<const float4*>(hs + (size_t)b * SEQ * HID);
    const float4  key = hb[lane];                               // hidden[b,0,:]
    const float4  wp  = reinterpret_cast<const float4*>(w)[lane];
    const float   bias = bp[0];

    #pragma unroll 1
    for (int j = 0; j < 25; ++j) {
        const int s = warp + 8 * j;
        float4 hv = hb[s * (HID / 4) + lane];
        float p = fast_tanh(hv.x + key.x) * wp.x
                + fast_tanh(hv.y + key.y) * wp.y
                + fast_tanh(hv.z + key.z) * wp.z
                + fast_tanh(hv.w + key.w) * wp.w;
        #pragma unroll
        for (int o = 16; o; o >>= 1) p += __shfl_xor_sync(0xffffffffu, p, o);
        if (lane == 0) s_scores[s] = p + bias;
    }
    __syncthreads();

    // masked softmax over S (thread t owns position t)
    int   my_id    = 0;
    bool  my_valid = false;
    float my_sc    = -INFINITY;
    if (tid < SEQ) {
        my_id    = ids[(size_t)b * SEQ + tid];
        my_valid = (my_id != PAD_ID) && (my_id != INTEREST_ID);
        my_sc    = my_valid ? s_scores[tid] : -INFINITY;
    }

    // block-reduce max
    float m = my_sc;
    #pragma unroll
    for (int o = 16; o; o >>= 1) m = fmaxf(m, __shfl_xor_sync(0xffffffffu, m, o));
    if (lane == 0) red[warp] = m;
    __syncthreads();
    if (warp == 0) {
        float mm = red[lane & 7];
        #pragma unroll
        for (int o = 4; o; o >>= 1) mm = fmaxf(mm, __shfl_xor_sync(0xffffffffu, mm, o));
        if (lane == 0) red[0] = mm;
    }
    __syncthreads();
    m = red[0];

    // exp and block-reduce sum (arg <= 0 after max-normalization, __expf safe)
    float e = (tid < SEQ && my_valid) ? __expf(my_sc - m) : 0.f;
    float ssum = e;
    #pragma unroll
    for (int o = 16; o; o >>= 1) ssum += __shfl_xor_sync(0xffffffffu, ssum, o);
    __syncthreads();
    if (lane == 0) red[warp] = ssum;
    __syncthreads();
    if (warp == 0) {
        float tt = red[lane & 7];
        #pragma unroll
        for (int o = 4; o; o >>= 1) tt += __shfl_xor_sync(0xffffffffu, tt, o);
        if (lane == 0) red[0] = tt;
    }
    __syncthreads();
    const float inv_sum = 1.0f / red[0];

    // scatter into this block's private (pre-zeroed) row
    if (tid < SEQ && my_valid) {
        atomicAdd(out + (size_t)b * VOCAB + my_id, e * inv_sum);
    }
}

extern "C" void kernel_launch(void* const* d_in, const int* in_sizes, int n_in,
                              void* d_out, int out_size) {
    const float* hs  = (const float*)d_in[0];
    const int*   ids = (const int*)d_in[1];
    const float* w   = (const float*)d_in[2];
    const float* bp  = (const float*)d_in[3];
    float*       out = (float*)d_out;

    // Driver-tuned zero-fill of the 410 MB output (graph memset node, ~6.8 TB/s).
    cudaMemsetAsync(out, 0, (size_t)out_size * sizeof(float));

    // Reads + scatter; ordered after the memset by stream order.
    score_scatter_kernel<<<BATCH, NTHR>>>(hs, ids, w, bp, out);
}

// round 10
// speedup vs baseline: 1.4592x; 1.0004x over previous
#include <cuda_runtime.h>
#include <math.h>

#define BATCH   1024
#define SEQ     200
#define HID     128
#define VOCAB   100000
#define PAD_ID      99998
#define INTEREST_ID 99999
#define NTHR    256

__device__ __forceinline__ float fast_tanh(float x) {
    float y;
    asm("tanh.approx.f32 %0, %1;" : "=f"(y) : "f"(x));
    return y;
}

// ---------------------------------------------------------------------------
// Fused: scores -> masked softmax -> scatter-add into (pre-zeroed) output.
// One CTA per batch row. ~106 MB of reads, 205K spread atomics.
// Score loop unrolled x5 for MLP (5 LDG.128 in flight per warp).
// ---------------------------------------------------------------------------
__global__ __launch_bounds__(NTHR, 6) void score_scatter_kernel(
    const float* __restrict__ hs,   // (B, S, H) fp32
    const int*   __restrict__ ids,  // (B, S) int32
    const float* __restrict__ w,    // (H,)
    const float* __restrict__ bp,   // (1,)
    float* __restrict__ out)        // (B, VOCAB) fp32, already zeroed
{
    const int b    = blockIdx.x;
    const int tid  = threadIdx.x;
    const int lane = tid & 31;
    const int warp = tid >> 5;

    __shared__ float s_scores[SEQ];
    __shared__ float red[8];

    // lane l owns H-elements [4l, 4l+4)
    const float4* hb  = reinterpret_cast<const float4*>(hs + (size_t)b * SEQ * HID);
    const float4  key = hb[lane];                               // hidden[b,0,:]
    const float4  wp  = reinterpret_cast<const float4*>(w)[lane];
    const float   bias = bp[0];

    // 25 s-rows per warp, 5 blocks of 5 -> 5 independent load+reduce chains
    #pragma unroll 1
    for (int jo = 0; jo < 25; jo += 5) {
        float4 hv[5];
        #pragma unroll
        for (int u = 0; u < 5; ++u) {
            const int s = warp + 8 * (jo + u);
            hv[u] = hb[s * (HID / 4) + lane];
        }
        float p[5];
        #pragma unroll
        for (int u = 0; u < 5; ++u) {
            p[u] = fast_tanh(hv[u].x + key.x) * wp.x
                 + fast_tanh(hv[u].y + key.y) * wp.y
                 + fast_tanh(hv[u].z + key.z) * wp.z
                 + fast_tanh(hv[u].w + key.w) * wp.w;
        }
        #pragma unroll
        for (int o = 16; o; o >>= 1) {
            #pragma unroll
            for (int u = 0; u < 5; ++u)
                p[u] += __shfl_xor_sync(0xffffffffu, p[u], o);
        }
        if (lane == 0) {
            #pragma unroll
            for (int u = 0; u < 5; ++u)
                s_scores[warp + 8 * (jo + u)] = p[u] + bias;
        }
    }
    __syncthreads();

    // masked softmax over S (thread t owns position t)
    int   my_id    = 0;
    bool  my_valid = false;
    float my_sc    = -INFINITY;
    if (tid < SEQ) {
        my_id    = ids[(size_t)b * SEQ + tid];
        my_valid = (my_id != PAD_ID) && (my_id != INTEREST_ID);
        my_sc    = my_valid ? s_scores[tid] : -INFINITY;
    }

    // block-reduce max
    float m = my_sc;
    #pragma unroll
    for (int o = 16; o; o >>= 1) m = fmaxf(m, __shfl_xor_sync(0xffffffffu, m, o));
    if (lane == 0) red[warp] = m;
    __syncthreads();
    if (warp == 0) {
        float mm = red[lane & 7];
        #pragma unroll
        for (int o = 4; o; o >>= 1) mm = fmaxf(mm, __shfl_xor_sync(0xffffffffu, mm, o));
        if (lane == 0) red[0] = mm;
    }
    __syncthreads();
    m = red[0];

    // exp and block-reduce sum (arg <= 0 after max-normalization, __expf safe)
    float e = (tid < SEQ && my_valid) ? __expf(my_sc - m) : 0.f;
    float ssum = e;
    #pragma unroll
    for (int o = 16; o; o >>= 1) ssum += __shfl_xor_sync(0xffffffffu, ssum, o);
    __syncthreads();
    if (lane == 0) red[warp] = ssum;
    __syncthreads();
    if (warp == 0) {
        float tt = red[lane & 7];
        #pragma unroll
        for (int o = 4; o; o >>= 1) tt += __shfl_xor_sync(0xffffffffu, tt, o);
        if (lane == 0) red[0] = tt;
    }
    __syncthreads();
    const float inv_sum = 1.0f / red[0];

    // scatter into this block's private (pre-zeroed) row
    if (tid < SEQ && my_valid) {
        atomicAdd(out + (size_t)b * VOCAB + my_id, e * inv_sum);
    }
}

extern "C" void kernel_launch(void* const* d_in, const int* in_sizes, int n_in,
                              void* d_out, int out_size) {
    const float* hs  = (const float*)d_in[0];
    const int*   ids = (const int*)d_in[1];
    const float* w   = (const float*)d_in[2];
    const float* bp  = (const float*)d_in[3];
    float*       out = (float*)d_out;

    // Driver-tuned zero-fill of the 410 MB output (graph memset node, ~6.8 TB/s).
    cudaMemsetAsync(out, 0, (size_t)out_size * sizeof(float));

    // Reads + scatter; ordered after the memset by stream order.
    score_scatter_kernel<<<BATCH, NTHR>>>(hs, ids, w, bp, out);
}

// round 11
// speedup vs baseline: 1.5286x; 1.0476x over previous
#include <cuda_runtime.h>
#include <math.h>

#define BATCH   1024
#define SEQ     200
#define HID     128
#define VOCAB   100000
#define PAD_ID      99998
#define INTEREST_ID 99999
#define NTHR    256

__device__ __forceinline__ float fast_tanh(float x) {
    float y;
    asm("tanh.approx.f32 %0, %1;" : "=f"(y) : "f"(x));
    return y;
}

// ---------------------------------------------------------------------------
// Fused: scores -> masked softmax (max-free; |score| <= ~9) -> scatter-add.
// One CTA per batch row. occ-8 friendly (regs capped at 32), unroll x2.
// ---------------------------------------------------------------------------
__global__ __launch_bounds__(NTHR, 8) void score_scatter_kernel(
    const float* __restrict__ hs,   // (B, S, H) fp32
    const int*   __restrict__ ids,  // (B, S) int32
    const float* __restrict__ w,    // (H,)
    const float* __restrict__ bp,   // (1,)
    float* __restrict__ out)        // (B, VOCAB) fp32, already zeroed
{
    const int b    = blockIdx.x;
    const int tid  = threadIdx.x;
    const int lane = tid & 31;
    const int warp = tid >> 5;

    __shared__ float s_scores[SEQ];
    __shared__ float red[8];

    // lane l owns H-elements [4l, 4l+4)
    const float4* hb  = reinterpret_cast<const float4*>(hs + (size_t)b * SEQ * HID);
    const float4  key = hb[lane];                               // hidden[b,0,:]
    const float4  wp  = reinterpret_cast<const float4*>(w)[lane];
    const float   bias = bp[0];

    // 25 s-rows per warp: 12 pairs (MLP=2) + 1 tail
    #pragma unroll 1
    for (int jo = 0; jo < 24; jo += 2) {
        const int s0 = warp + 8 * jo;
        const int s1 = warp + 8 * (jo + 1);
        float4 h0 = hb[s0 * (HID / 4) + lane];
        float4 h1 = hb[s1 * (HID / 4) + lane];
        float p0 = fast_tanh(h0.x + key.x) * wp.x
                 + fast_tanh(h0.y + key.y) * wp.y
                 + fast_tanh(h0.z + key.z) * wp.z
                 + fast_tanh(h0.w + key.w) * wp.w;
        float p1 = fast_tanh(h1.x + key.x) * wp.x
                 + fast_tanh(h1.y + key.y) * wp.y
                 + fast_tanh(h1.z + key.z) * wp.z
                 + fast_tanh(h1.w + key.w) * wp.w;
        #pragma unroll
        for (int o = 16; o; o >>= 1) {
            p0 += __shfl_xor_sync(0xffffffffu, p0, o);
            p1 += __shfl_xor_sync(0xffffffffu, p1, o);
        }
        if (lane == 0) {
            s_scores[s0] = p0 + bias;
            s_scores[s1] = p1 + bias;
        }
    }
    {   // tail: j = 24
        const int s = warp + 8 * 24;
        float4 hv = hb[s * (HID / 4) + lane];
        float p = fast_tanh(hv.x + key.x) * wp.x
                + fast_tanh(hv.y + key.y) * wp.y
                + fast_tanh(hv.z + key.z) * wp.z
                + fast_tanh(hv.w + key.w) * wp.w;
        #pragma unroll
        for (int o = 16; o; o >>= 1) p += __shfl_xor_sync(0xffffffffu, p, o);
        if (lane == 0) s_scores[s] = p + bias;
    }
    __syncthreads();

    // ---- max-free masked softmax (|score| <= ~9, exp never overflows) ----
    int   my_id = 0;
    float e     = 0.f;
    if (tid < SEQ) {
        my_id = ids[(size_t)b * SEQ + tid];
        const bool valid = (my_id != PAD_ID) && (my_id != INTEREST_ID);
        e = valid ? __expf(s_scores[tid]) : 0.f;
    }

    // single block-reduce: sum of e
    float ssum = e;
    #pragma unroll
    for (int o = 16; o; o >>= 1) ssum += __shfl_xor_sync(0xffffffffu, ssum, o);
    if (lane == 0) red[warp] = ssum;
    __syncthreads();
    if (warp == 0) {
        float tt = red[lane & 7];
        #pragma unroll
        for (int o = 4; o; o >>= 1) tt += __shfl_xor_sync(0xffffffffu, tt, o);
        if (lane == 0) red[0] = tt;
    }
    __syncthreads();
    const float inv_sum = 1.0f / red[0];

    // scatter into this block's private (pre-zeroed) row
    if (e != 0.f) {
        atomicAdd(out + (size_t)b * VOCAB + my_id, e * inv_sum);
    }
}

extern "C" void kernel_launch(void* const* d_in, const int* in_sizes, int n_in,
                              void* d_out, int out_size) {
    const float* hs  = (const float*)d_in[0];
    const int*   ids = (const int*)d_in[1];
    const float* w   = (const float*)d_in[2];
    const float* bp  = (const float*)d_in[3];
    float*       out = (float*)d_out;

    // Driver-tuned zero-fill of the 410 MB output (graph memset node, ~6.8 TB/s).
    cudaMemsetAsync(out, 0, (size_t)out_size * sizeof(float));

    // Reads + scatter; ordered after the memset by stream order.
    score_scatter_kernel<<<BATCH, NTHR>>>(hs, ids, w, bp, out);
}

// round 12
// speedup vs baseline: 1.5535x; 1.0162x over previous
#include <cuda_runtime.h>
#include <math.h>

#define BATCH   1024
#define SEQ     200
#define HID     128
#define VOCAB   100000
#define PAD_ID      99998
#define INTEREST_ID 99999
#define NTHR    256

__device__ __forceinline__ float fast_tanh(float x) {
    float y;
    asm("tanh.approx.f32 %0, %1;" : "=f"(y) : "f"(x));
    return y;
}

// ---------------------------------------------------------------------------
// Fused: scores -> masked softmax (max-free; |score| <= ~9) -> scatter-add.
// One CTA per batch row. occ-7 (148*7=1036 slots, 1024 CTAs -> 98.8% fill),
// unroll x3 for MLP=3 per warp.
// ---------------------------------------------------------------------------
__global__ __launch_bounds__(NTHR, 7) void score_scatter_kernel(
    const float* __restrict__ hs,   // (B, S, H) fp32
    const int*   __restrict__ ids,  // (B, S) int32
    const float* __restrict__ w,    // (H,)
    const float* __restrict__ bp,   // (1,)
    float* __restrict__ out)        // (B, VOCAB) fp32, already zeroed
{
    const int b    = blockIdx.x;
    const int tid  = threadIdx.x;
    const int lane = tid & 31;
    const int warp = tid >> 5;

    __shared__ float s_scores[SEQ];
    __shared__ float red[8];

    // lane l owns H-elements [4l, 4l+4)
    const float4* hb  = reinterpret_cast<const float4*>(hs + (size_t)b * SEQ * HID);
    const float4  key = hb[lane];                               // hidden[b,0,:]
    const float4  wp  = reinterpret_cast<const float4*>(w)[lane];
    const float   bias = bp[0];

    // 25 s-rows per warp: 8 triples (MLP=3) + 1 tail
    #pragma unroll 1
    for (int jo = 0; jo < 24; jo += 3) {
        float4 hv[3];
        #pragma unroll
        for (int u = 0; u < 3; ++u)
            hv[u] = hb[(warp + 8 * (jo + u)) * (HID / 4) + lane];

        float p[3];
        #pragma unroll
        for (int u = 0; u < 3; ++u) {
            p[u] = fast_tanh(hv[u].x + key.x) * wp.x
                 + fast_tanh(hv[u].y + key.y) * wp.y
                 + fast_tanh(hv[u].z + key.z) * wp.z
                 + fast_tanh(hv[u].w + key.w) * wp.w;
        }
        #pragma unroll
        for (int o = 16; o; o >>= 1) {
            #pragma unroll
            for (int u = 0; u < 3; ++u)
                p[u] += __shfl_xor_sync(0xffffffffu, p[u], o);
        }
        if (lane == 0) {
            #pragma unroll
            for (int u = 0; u < 3; ++u)
                s_scores[warp + 8 * (jo + u)] = p[u] + bias;
        }
    }
    {   // tail: j = 24
        const int s = warp + 8 * 24;
        float4 hv = hb[s * (HID / 4) + lane];
        float p = fast_tanh(hv.x + key.x) * wp.x
                + fast_tanh(hv.y + key.y) * wp.y
                + fast_tanh(hv.z + key.z) * wp.z
                + fast_tanh(hv.w + key.w) * wp.w;
        #pragma unroll
        for (int o = 16; o; o >>= 1) p += __shfl_xor_sync(0xffffffffu, p, o);
        if (lane == 0) s_scores[s] = p + bias;
    }
    __syncthreads();

    // ---- max-free masked softmax (|score| <= ~9, exp never overflows) ----
    int   my_id = 0;
    float e     = 0.f;
    if (tid < SEQ) {
        my_id = ids[(size_t)b * SEQ + tid];
        const bool valid = (my_id != PAD_ID) && (my_id != INTEREST_ID);
        e = valid ? __expf(s_scores[tid]) : 0.f;
    }

    // single block-reduce: sum of e
    float ssum = e;
    #pragma unroll
    for (int o = 16; o; o >>= 1) ssum += __shfl_xor_sync(0xffffffffu, ssum, o);
    if (lane == 0) red[warp] = ssum;
    __syncthreads();
    if (warp == 0) {
        float tt = red[lane & 7];
        #pragma unroll
        for (int o = 4; o; o >>= 1) tt += __shfl_xor_sync(0xffffffffu, tt, o);
        if (lane == 0) red[0] = tt;
    }
    __syncthreads();
    const float inv_sum = 1.0f / red[0];

    // scatter into this block's private (pre-zeroed) row
    if (e != 0.f) {
        atomicAdd(out + (size_t)b * VOCAB + my_id, e * inv_sum);
    }
}

extern "C" void kernel_launch(void* const* d_in, const int* in_sizes, int n_in,
                              void* d_out, int out_size) {
    const float* hs  = (const float*)d_in[0];
    const int*   ids = (const int*)d_in[1];
    const float* w   = (const float*)d_in[2];
    const float* bp  = (const float*)d_in[3];
    float*       out = (float*)d_out;

    // Driver-tuned zero-fill of the 410 MB output (graph memset node, ~6.8 TB/s).
    cudaMemsetAsync(out, 0, (size_t)out_size * sizeof(float));

    // Reads + scatter; ordered after the memset by stream order.
    score_scatter_kernel<<<BATCH, NTHR>>>(hs, ids, w, bp, out);
}